// round 14
// baseline (speedup 1.0000x reference)
#include <cuda_runtime.h>
#include <cuda_bf16.h>

#define NN 2048
#define LOG2F_ 0.69314718055994530942f

typedef unsigned long long ull;

// Scratch (__device__ globals; no cudaMalloc allowed)
// 3-term split bf16 rows: [n][0..31]=hi, [32..63]=mid, [64..95]=lo (192B rows).
// Full K=96 bf16 dot == (hi+mid+lo).(hi+mid+lo) ~= fp32 dot to ~1e-7 rel.
__device__ __align__(16) __nv_bfloat16 g_Ahl[NN * 96];  // M2 (i side / MMA A)
__device__ __align__(16) __nv_bfloat16 g_Bhl[NN * 96];  // M1 (j side / MMA B)
__device__ float g_partial[32 * NN];  // [(jtile*2+colhalf)][row] softplus sums
__device__ float g_diag[NN];          // raw u_ii
__device__ unsigned g_ticket = 0;     // last-block ticket (monotone, %512)

// ---- packed f32x2 helpers ----
__device__ __forceinline__ ull pack2(float x, float y) {
    ull r;
    asm("mov.b64 %0, {%1, %2};" : "=l"(r) : "r"(__float_as_uint(x)), "r"(__float_as_uint(y)));
    return r;
}
__device__ __forceinline__ void unpack2(ull v, float& x, float& y) {
    unsigned lo, hi;
    asm("mov.b64 {%0, %1}, %2;" : "=r"(lo), "=r"(hi) : "l"(v));
    x = __uint_as_float(lo); y = __uint_as_float(hi);
}
__device__ __forceinline__ ull ffma2(ull a, ull b, ull c) {
    ull d;
    asm("fma.rn.f32x2 %0, %1, %2, %3;" : "=l"(d) : "l"(a), "l"(b), "l"(c));
    return d;
}
__device__ __forceinline__ float softplus_f(float x) {
    float a = fabsf(x);
    float l = __logf(1.f + __expf(-a));
    return fmaxf(x, 0.f) + l;
}

// warp-level bf16 tensor-core mma: D(16x8,f32) += A(16x16,bf16) x B(16x8,bf16)
__device__ __forceinline__ void mma16816(float* c, const unsigned* a,
                                         const unsigned* b) {
    asm volatile(
        "mma.sync.aligned.m16n8k16.row.col.f32.bf16.bf16.f32 "
        "{%0,%1,%2,%3}, {%4,%5,%6,%7}, {%8,%9}, {%0,%1,%2,%3};"
        : "+f"(c[0]), "+f"(c[1]), "+f"(c[2]), "+f"(c[3])
        : "r"(a[0]), "r"(a[1]), "r"(a[2]), "r"(a[3]), "r"(b[0]), "r"(b[1]));
}

// split v into hi/mid/lo bf16 components
__device__ __forceinline__ void split3(float v, __nv_bfloat16& h,
                                       __nv_bfloat16& m, __nv_bfloat16& l) {
    h = __float2bfloat16(v);
    float r1 = v - __bfloat162float(h);
    m = __float2bfloat16(r1);
    l = __float2bfloat16(r1 - __bfloat162float(m));
}

// ---- embed smem layout (static 45.3KB, aliased regions) ----
#define SM_IN    0
#define SM_SP1   10240
#define SM_SP2   26624
#define SM_PART  34816
#define SM_SB1   45056
#define SM_SB2   45184
#define SM_TOTAL 45312

// ---------------------------------------------------------------------------
// Kernel 1 (v5 + 3-term bf16 emit): embeddings + leaky_relu + agent-mean.
// ---------------------------------------------------------------------------
__global__ void __launch_bounds__(256) embed_kernel(
    const float* __restrict__ state, const float* __restrict__ action,
    const float* __restrict__ W1, const float* __restrict__ b1,
    const float* __restrict__ W2, const float* __restrict__ b2) {
    __shared__ __align__(16) char smem[SM_TOTAL];
    float* sIN = (float*)(smem + SM_IN);
    ull   (*sP1)[32] = (ull (*)[32])(smem + SM_SP1);
    ull   (*sP2)[32] = (ull (*)[32])(smem + SM_SP2);
    float (*spart)[4][5][32] = (float (*)[4][5][32])(smem + SM_PART);
    float* sb1 = (float*)(smem + SM_SB1);
    float* sb2 = (float*)(smem + SM_SB2);

    const int tid = threadIdx.x;

    #pragma unroll
    for (int i = 0; i < 8; i++) {
        int idx = tid + i * 256;
        int k2 = idx >> 5, u = idx & 31;
        sP1[k2][u] = pack2(W1[k2 * 64 + u], W1[k2 * 64 + 32 + u]);
    }
    #pragma unroll
    for (int i = 0; i < 4; i++) {
        int idx = tid + i * 256;
        int k2 = idx >> 5, u = idx & 31;
        sP2[k2][u] = pack2(W2[k2 * 64 + u], W2[k2 * 64 + 32 + u]);
    }
    {   // stage state tile: 4 samples x 640 floats, coalesced
        const float4* sg = (const float4*)(state + (size_t)blockIdx.x * 2560);
        float4* si4 = (float4*)sIN;
        si4[tid]       = sg[tid];
        si4[tid + 256] = sg[tid + 256];
        if (tid < 128) si4[tid + 512] = sg[tid + 512];
    }
    if (tid < 32) { sb1[tid] = b1[tid]; sb2[tid] = b2[tid]; }
    __syncthreads();

    const int nl = tid >> 6, kq = (tid >> 4) & 3, uh = tid & 15;
    const int n8 = blockIdx.x * 4;

    // ---------------- GEMM1: state @ W1, K-quarter (32 of 128) ------------
    {
        const float* base = sIN + nl * 640 + kq * 32;
        ull acc[5][2];
        #pragma unroll
        for (int a = 0; a < 5; a++) { acc[a][0] = 0ull; acc[a][1] = 0ull; }

        #pragma unroll
        for (int k4 = 0; k4 < 8; k4++) {
            ulonglong2 x[5];
            #pragma unroll
            for (int a = 0; a < 5; a++)
                x[a] = *(const ulonglong2*)(base + a * 128 + k4 * 4);
            const int k2 = kq * 16 + k4 * 2;
            ulonglong2 w0 = *(const ulonglong2*)&sP1[k2][2 * uh];
            ulonglong2 w1 = *(const ulonglong2*)&sP1[k2 + 1][2 * uh];
            #pragma unroll
            for (int a = 0; a < 5; a++) {
                acc[a][0] = ffma2(x[a].x, w0.x, acc[a][0]);
                acc[a][0] = ffma2(x[a].y, w1.x, acc[a][0]);
                acc[a][1] = ffma2(x[a].x, w0.y, acc[a][1]);
                acc[a][1] = ffma2(x[a].y, w1.y, acc[a][1]);
            }
        }
        #pragma unroll
        for (int a = 0; a < 5; a++) {
            float x0, x1, y0, y1;
            unpack2(acc[a][0], x0, x1);
            unpack2(acc[a][1], y0, y1);
            *(float2*)&spart[nl][kq][a][2 * uh] = make_float2(x0 + x1, y0 + y1);
        }
    }
    __syncthreads();

    // finalize1 (threads 0..127) + restage action (threads 128..255)
    if (tid < 128) {
        const int fu = tid >> 2, fnl = tid & 3;
        const int fn = n8 + fnl;
        float m = 0.f;
        #pragma unroll
        for (int a = 0; a < 5; a++) {
            float v = sb1[fu];
            #pragma unroll
            for (int q = 0; q < 4; q++) v += spart[fnl][q][a][fu];
            m += (v > 0.f) ? v : 0.01f * v;          // leaky_relu(0.01)
        }
        float v1 = 0.2f * m;
        __nv_bfloat16 h, md, lo;
        split3(v1, h, md, lo);
        g_Bhl[fn * 96 + fu]      = h;
        g_Bhl[fn * 96 + 32 + fu] = md;
        g_Bhl[fn * 96 + 64 + fu] = lo;
    } else {
        const int t = tid - 128;
        const float4* ag = (const float4*)(action + (size_t)blockIdx.x * 1280);
        float4* si4 = (float4*)sIN;
        si4[t]       = ag[t];
        si4[t + 128] = ag[t + 128];
        if (t < 64) si4[t + 256] = ag[t + 256];
    }
    __syncthreads();

    // ---------------- GEMM2: action @ W2, K-quarter (16 of 64) ------------
    {
        const float* base = sIN + nl * 320 + kq * 16;
        ull acc[5][2];
        #pragma unroll
        for (int a = 0; a < 5; a++) { acc[a][0] = 0ull; acc[a][1] = 0ull; }

        #pragma unroll
        for (int k4 = 0; k4 < 4; k4++) {
            ulonglong2 x[5];
            #pragma unroll
            for (int a = 0; a < 5; a++)
                x[a] = *(const ulonglong2*)(base + a * 64 + k4 * 4);
            const int k2 = kq * 8 + k4 * 2;
            ulonglong2 w0 = *(const ulonglong2*)&sP2[k2][2 * uh];
            ulonglong2 w1 = *(const ulonglong2*)&sP2[k2 + 1][2 * uh];
            #pragma unroll
            for (int a = 0; a < 5; a++) {
                acc[a][0] = ffma2(x[a].x, w0.x, acc[a][0]);
                acc[a][0] = ffma2(x[a].y, w1.x, acc[a][0]);
                acc[a][1] = ffma2(x[a].x, w0.y, acc[a][1]);
                acc[a][1] = ffma2(x[a].y, w1.y, acc[a][1]);
            }
        }
        __syncthreads();
        #pragma unroll
        for (int a = 0; a < 5; a++) {
            float x0, x1, y0, y1;
            unpack2(acc[a][0], x0, x1);
            unpack2(acc[a][1], y0, y1);
            *(float2*)&spart[nl][kq][a][2 * uh] = make_float2(x0 + x1, y0 + y1);
        }
    }
    __syncthreads();

    if (tid < 128) {
        const int fu = tid >> 2, fnl = tid & 3;
        const int fn = n8 + fnl;
        float m = 0.f;
        #pragma unroll
        for (int a = 0; a < 5; a++) {
            float v = sb2[fu];
            #pragma unroll
            for (int q = 0; q < 4; q++) v += spart[fnl][q][a][fu];
            m += (v > 0.f) ? v : 0.01f * v;
        }
        float v2 = 0.2f * m;
        __nv_bfloat16 h, md, lo;
        split3(v2, h, md, lo);
        g_Ahl[fn * 96 + fu]      = h;
        g_Ahl[fn * 96 + 32 + fu] = md;
        g_Ahl[fn * 96 + 64 + fu] = lo;
    }
}

// ---------------------------------------------------------------------------
// Kernel 2 (v8, mma.sync, K=96, occupancy-tuned): u = A.B^T.
// Grid 512 = 32 i-tiles(64 rows) x 16 j-tiles(128 cols). Block 256 thr:
// warp w -> rows (w&3)*16..+15, col half (w>>2)*64. 6 ksteps x 8 nblocks of
// mma.m16n8k16 -> acc 32 regs; launch_bounds(256,4). TSTRIDE=208 gives
// conflict-free fragment LDS (grp*52+four covers 32 distinct banks).
// Epilogue: batched softplus (prod<=2^16), quad shfl-reduce, diag capture,
// last-block ticket finalize.
// ---------------------------------------------------------------------------
#define TSTRIDE 208
__global__ void __launch_bounds__(256, 4) jsd_kernel(float* __restrict__ out) {
    __shared__ __align__(16) char sA[64 * TSTRIDE];    // 13 KB
    __shared__ __align__(16) char sB[128 * TSTRIDE];   // 26 KB
    __shared__ unsigned s_last;

    const int tid = threadIdx.x;
    const int w = tid >> 5, lane = tid & 31;
    const int ib = blockIdx.x >> 4, q = blockIdx.x & 15;
    const int i0 = ib * 64, j0 = q * 128;

    // stage tiles: 192B rows = 12 x 16B granules
    #pragma unroll
    for (int t = 0; t < 3; t++) {                    // A: 64*12 = 768 granules
        int idx = tid + t * 256;
        int row = idx / 12, g = idx - row * 12;
        *(uint4*)(sA + row * TSTRIDE + g * 16) =
            *(const uint4*)&g_Ahl[(i0 + row) * 96 + g * 8];
    }
    #pragma unroll
    for (int t = 0; t < 6; t++) {                    // B: 128*12 = 1536 granules
        int idx = tid + t * 256;
        int row = idx / 12, g = idx - row * 12;
        *(uint4*)(sB + row * TSTRIDE + g * 16) =
            *(const uint4*)&g_Bhl[(j0 + row) * 96 + g * 8];
    }
    __syncthreads();

    const int wr = w & 3, ch = w >> 2;               // row group, col half
    const int grp = lane >> 2, four = lane & 3;      // fragment coords

    float acc[8][4];
    #pragma unroll
    for (int nb = 0; nb < 8; nb++)
        #pragma unroll
        for (int p = 0; p < 4; p++) acc[nb][p] = 0.f;

    const char* arow0 = sA + (wr * 16 + grp) * TSTRIDE + four * 4;
    const char* brow0 = sB + (ch * 64 + grp) * TSTRIDE + four * 4;

    #pragma unroll
    for (int ks = 0; ks < 6; ks++) {                 // K = 6 x 16
        const int kb = ks * 32;
        unsigned afr[4];
        afr[0] = *(const unsigned*)(arow0 + kb);
        afr[1] = *(const unsigned*)(arow0 + 8 * TSTRIDE + kb);
        afr[2] = *(const unsigned*)(arow0 + kb + 16);
        afr[3] = *(const unsigned*)(arow0 + 8 * TSTRIDE + kb + 16);
        #pragma unroll
        for (int nb = 0; nb < 8; nb++) {
            unsigned bfr[2];
            const char* bp = brow0 + nb * 8 * TSTRIDE + kb;
            bfr[0] = *(const unsigned*)(bp);
            bfr[1] = *(const unsigned*)(bp + 16);
            mma16816(acc[nb], afr, bfr);
        }
    }

    // epilogue: rows rA (c0,c1) / rA+8 (c2,c3); cols j0+ch*64+nb*8+2*four+{0,1}
    const int rA = i0 + wr * 16 + grp;
    const int rB = rA + 8;
    const bool dtile = ((ib >> 1) == q);             // tile contains diagonal
    float linA = 0.f, prodA = 1.f, linB = 0.f, prodB = 1.f;
    #pragma unroll
    for (int nb = 0; nb < 8; nb++) {
        const int col = j0 + ch * 64 + nb * 8 + 2 * four;
        float c0 = acc[nb][0], c1 = acc[nb][1];
        float c2 = acc[nb][2], c3 = acc[nb][3];
        if (dtile) {
            if (col == rA)     g_diag[rA] = c0;      // single writer each
            if (col + 1 == rA) g_diag[rA] = c1;
            if (col == rB)     g_diag[rB] = c2;
            if (col + 1 == rB) g_diag[rB] = c3;
        }
        linA  += fmaxf(c0, 0.f) + fmaxf(c1, 0.f);
        prodA *= (1.f + __expf(-fabsf(c0))) * (1.f + __expf(-fabsf(c1)));
        linB  += fmaxf(c2, 0.f) + fmaxf(c3, 0.f);
        prodB *= (1.f + __expf(-fabsf(c2))) * (1.f + __expf(-fabsf(c3)));
    }
    float sAr = linA + __logf(prodA);                // 16 softplus, 1 log
    float sBr = linB + __logf(prodB);

    // reduce across the 4 lanes of the quad sharing each row
    sAr += __shfl_xor_sync(0xffffffffu, sAr, 1);
    sAr += __shfl_xor_sync(0xffffffffu, sAr, 2);
    sBr += __shfl_xor_sync(0xffffffffu, sBr, 1);
    sBr += __shfl_xor_sync(0xffffffffu, sBr, 2);
    if (four == 0) {
        g_partial[(q * 2 + ch) * NN + rA] = sAr;
        g_partial[(q * 2 + ch) * NN + rB] = sBr;
    }

    // ---- last-block finalize (threadFenceReduction pattern) ----
    __threadfence();                                 // publish partials + diag
    __syncthreads();
    if (tid == 0) {
        unsigned old = atomicAdd(&g_ticket, 1u);
        s_last = ((old & 511u) == 511u) ? 1u : 0u;   // grid == 512 exactly
    }
    __syncthreads();
    if (s_last) {
        __threadfence();                             // acquire others' writes
        #pragma unroll
        for (int r = 0; r < 8; r++) {
            const int i = tid + r * 256;
            float tot = 0.f;
            #pragma unroll
            for (int p = 0; p < 32; p++) tot += g_partial[p * NN + i];
            float ud  = g_diag[i];
            float spd = softplus_f(ud);
            float Eneg = (tot - spd - 2047.f * LOG2F_) * (1.f / 2047.f);
            float Epos = LOG2F_ - spd + ud;          // = log2 - softplus(-u_ii)
            out[i]      = Eneg - Epos;               // loss
            out[NN + i] = Epos;                      // MI
        }
    }
}

extern "C" void kernel_launch(void* const* d_in, const int* in_sizes, int n_in,
                              void* d_out, int out_size) {
    const float* state  = (const float*)d_in[0];
    const float* action = (const float*)d_in[1];
    const float* W1     = (const float*)d_in[2];
    const float* b1     = (const float*)d_in[3];
    const float* W2     = (const float*)d_in[4];
    const float* b2     = (const float*)d_in[5];
    float* out = (float*)d_out;

    embed_kernel<<<NN / 4, 256>>>(state, action, W1, b1, W2, b2);
    jsd_kernel<<<512, 256>>>(out);
}

// round 15
// speedup vs baseline: 1.0605x; 1.0605x over previous
#include <cuda_runtime.h>
#include <cuda_bf16.h>

#define NN 2048
#define LOG2F_ 0.69314718055994530942f

typedef unsigned long long ull;

// Scratch (__device__ globals; no cudaMalloc allowed)
// 2-term split bf16 rows: [n][0..31]=hi, [n][32..63]=mid (128B rows).
// jsd computes u = hi.hi + hi.mid + mid.hi (cross terms INCLUDED via
// fragment reuse); residual error ~ mid.mid ~ 2^-18 |u|.
__device__ __align__(16) __nv_bfloat16 g_Ahl[NN * 64];  // M2 (i side / MMA A)
__device__ __align__(16) __nv_bfloat16 g_Bhl[NN * 64];  // M1 (j side / MMA B)
__device__ float g_partial[16 * NN];  // [jtile][row] softplus row sums
__device__ float g_diag[NN];          // raw u_ii
__device__ unsigned g_ticket = 0;     // last-block ticket (monotone, %256)

// ---- packed f32x2 helpers ----
__device__ __forceinline__ ull pack2(float x, float y) {
    ull r;
    asm("mov.b64 %0, {%1, %2};" : "=l"(r) : "r"(__float_as_uint(x)), "r"(__float_as_uint(y)));
    return r;
}
__device__ __forceinline__ void unpack2(ull v, float& x, float& y) {
    unsigned lo, hi;
    asm("mov.b64 {%0, %1}, %2;" : "=r"(lo), "=r"(hi) : "l"(v));
    x = __uint_as_float(lo); y = __uint_as_float(hi);
}
__device__ __forceinline__ ull ffma2(ull a, ull b, ull c) {
    ull d;
    asm("fma.rn.f32x2 %0, %1, %2, %3;" : "=l"(d) : "l"(a), "l"(b), "l"(c));
    return d;
}
__device__ __forceinline__ float softplus_f(float x) {
    float a = fabsf(x);
    float l = __logf(1.f + __expf(-a));
    return fmaxf(x, 0.f) + l;
}

// warp-level bf16 tensor-core mma: D(16x8,f32) += A(16x16,bf16) x B(16x8,bf16)
__device__ __forceinline__ void mma16816(float* c, const unsigned* a,
                                         const unsigned* b) {
    asm volatile(
        "mma.sync.aligned.m16n8k16.row.col.f32.bf16.bf16.f32 "
        "{%0,%1,%2,%3}, {%4,%5,%6,%7}, {%8,%9}, {%0,%1,%2,%3};"
        : "+f"(c[0]), "+f"(c[1]), "+f"(c[2]), "+f"(c[3])
        : "r"(a[0]), "r"(a[1]), "r"(a[2]), "r"(a[3]), "r"(b[0]), "r"(b[1]));
}

// ldmatrix x4: each thread supplies one row address; lanes 8i..8i+7 feed
// matrix i -> reg r[i]. Fragment layout matches mma operand layout exactly.
#define LDM_X4(r, addr) \
    asm volatile("ldmatrix.sync.aligned.m8n8.x4.shared.b16 {%0,%1,%2,%3}, [%4];" \
        : "=r"((r)[0]), "=r"((r)[1]), "=r"((r)[2]), "=r"((r)[3]) : "r"(addr))

__device__ __forceinline__ unsigned smem_u32(const void* p) {
    unsigned a;
    asm("{ .reg .u64 t; cvta.to.shared.u64 t, %1; cvt.u32.u64 %0, t; }"
        : "=r"(a) : "l"(p));
    return a;
}

// ---- embed smem layout (static 45.3KB, aliased regions) ----
#define SM_IN    0
#define SM_SP1   10240
#define SM_SP2   26624
#define SM_PART  34816
#define SM_SB1   45056
#define SM_SB2   45184
#define SM_TOTAL 45312

// ---------------------------------------------------------------------------
// Kernel 1 (v5 + 2-term bf16 emit): embeddings + leaky_relu + agent-mean.
// ---------------------------------------------------------------------------
__global__ void __launch_bounds__(256) embed_kernel(
    const float* __restrict__ state, const float* __restrict__ action,
    const float* __restrict__ W1, const float* __restrict__ b1,
    const float* __restrict__ W2, const float* __restrict__ b2) {
    __shared__ __align__(16) char smem[SM_TOTAL];
    float* sIN = (float*)(smem + SM_IN);
    ull   (*sP1)[32] = (ull (*)[32])(smem + SM_SP1);
    ull   (*sP2)[32] = (ull (*)[32])(smem + SM_SP2);
    float (*spart)[4][5][32] = (float (*)[4][5][32])(smem + SM_PART);
    float* sb1 = (float*)(smem + SM_SB1);
    float* sb2 = (float*)(smem + SM_SB2);

    const int tid = threadIdx.x;

    #pragma unroll
    for (int i = 0; i < 8; i++) {
        int idx = tid + i * 256;
        int k2 = idx >> 5, u = idx & 31;
        sP1[k2][u] = pack2(W1[k2 * 64 + u], W1[k2 * 64 + 32 + u]);
    }
    #pragma unroll
    for (int i = 0; i < 4; i++) {
        int idx = tid + i * 256;
        int k2 = idx >> 5, u = idx & 31;
        sP2[k2][u] = pack2(W2[k2 * 64 + u], W2[k2 * 64 + 32 + u]);
    }
    {   // stage state tile: 4 samples x 640 floats, coalesced
        const float4* sg = (const float4*)(state + (size_t)blockIdx.x * 2560);
        float4* si4 = (float4*)sIN;
        si4[tid]       = sg[tid];
        si4[tid + 256] = sg[tid + 256];
        if (tid < 128) si4[tid + 512] = sg[tid + 512];
    }
    if (tid < 32) { sb1[tid] = b1[tid]; sb2[tid] = b2[tid]; }
    __syncthreads();

    const int nl = tid >> 6, kq = (tid >> 4) & 3, uh = tid & 15;
    const int n8 = blockIdx.x * 4;

    // ---------------- GEMM1: state @ W1, K-quarter (32 of 128) ------------
    {
        const float* base = sIN + nl * 640 + kq * 32;
        ull acc[5][2];
        #pragma unroll
        for (int a = 0; a < 5; a++) { acc[a][0] = 0ull; acc[a][1] = 0ull; }

        #pragma unroll
        for (int k4 = 0; k4 < 8; k4++) {
            ulonglong2 x[5];
            #pragma unroll
            for (int a = 0; a < 5; a++)
                x[a] = *(const ulonglong2*)(base + a * 128 + k4 * 4);
            const int k2 = kq * 16 + k4 * 2;
            ulonglong2 w0 = *(const ulonglong2*)&sP1[k2][2 * uh];
            ulonglong2 w1 = *(const ulonglong2*)&sP1[k2 + 1][2 * uh];
            #pragma unroll
            for (int a = 0; a < 5; a++) {
                acc[a][0] = ffma2(x[a].x, w0.x, acc[a][0]);
                acc[a][0] = ffma2(x[a].y, w1.x, acc[a][0]);
                acc[a][1] = ffma2(x[a].x, w0.y, acc[a][1]);
                acc[a][1] = ffma2(x[a].y, w1.y, acc[a][1]);
            }
        }
        #pragma unroll
        for (int a = 0; a < 5; a++) {
            float x0, x1, y0, y1;
            unpack2(acc[a][0], x0, x1);
            unpack2(acc[a][1], y0, y1);
            *(float2*)&spart[nl][kq][a][2 * uh] = make_float2(x0 + x1, y0 + y1);
        }
    }
    __syncthreads();

    // finalize1 (threads 0..127) + restage action (threads 128..255)
    if (tid < 128) {
        const int fu = tid >> 2, fnl = tid & 3;
        const int fn = n8 + fnl;
        float m = 0.f;
        #pragma unroll
        for (int a = 0; a < 5; a++) {
            float v = sb1[fu];
            #pragma unroll
            for (int q = 0; q < 4; q++) v += spart[fnl][q][a][fu];
            m += (v > 0.f) ? v : 0.01f * v;          // leaky_relu(0.01)
        }
        float v1 = 0.2f * m;
        __nv_bfloat16 h = __float2bfloat16(v1);
        g_Bhl[fn * 64 + fu]      = h;
        g_Bhl[fn * 64 + 32 + fu] = __float2bfloat16(v1 - __bfloat162float(h));
    } else {
        const int t = tid - 128;
        const float4* ag = (const float4*)(action + (size_t)blockIdx.x * 1280);
        float4* si4 = (float4*)sIN;
        si4[t]       = ag[t];
        si4[t + 128] = ag[t + 128];
        if (t < 64) si4[t + 256] = ag[t + 256];
    }
    __syncthreads();

    // ---------------- GEMM2: action @ W2, K-quarter (16 of 64) ------------
    {
        const float* base = sIN + nl * 320 + kq * 16;
        ull acc[5][2];
        #pragma unroll
        for (int a = 0; a < 5; a++) { acc[a][0] = 0ull; acc[a][1] = 0ull; }

        #pragma unroll
        for (int k4 = 0; k4 < 4; k4++) {
            ulonglong2 x[5];
            #pragma unroll
            for (int a = 0; a < 5; a++)
                x[a] = *(const ulonglong2*)(base + a * 64 + k4 * 4);
            const int k2 = kq * 8 + k4 * 2;
            ulonglong2 w0 = *(const ulonglong2*)&sP2[k2][2 * uh];
            ulonglong2 w1 = *(const ulonglong2*)&sP2[k2 + 1][2 * uh];
            #pragma unroll
            for (int a = 0; a < 5; a++) {
                acc[a][0] = ffma2(x[a].x, w0.x, acc[a][0]);
                acc[a][0] = ffma2(x[a].y, w1.x, acc[a][0]);
                acc[a][1] = ffma2(x[a].x, w0.y, acc[a][1]);
                acc[a][1] = ffma2(x[a].y, w1.y, acc[a][1]);
            }
        }
        __syncthreads();
        #pragma unroll
        for (int a = 0; a < 5; a++) {
            float x0, x1, y0, y1;
            unpack2(acc[a][0], x0, x1);
            unpack2(acc[a][1], y0, y1);
            *(float2*)&spart[nl][kq][a][2 * uh] = make_float2(x0 + x1, y0 + y1);
        }
    }
    __syncthreads();

    if (tid < 128) {
        const int fu = tid >> 2, fnl = tid & 3;
        const int fn = n8 + fnl;
        float m = 0.f;
        #pragma unroll
        for (int a = 0; a < 5; a++) {
            float v = sb2[fu];
            #pragma unroll
            for (int q = 0; q < 4; q++) v += spart[fnl][q][a][fu];
            m += (v > 0.f) ? v : 0.01f * v;
        }
        float v2 = 0.2f * m;
        __nv_bfloat16 h = __float2bfloat16(v2);
        g_Ahl[fn * 64 + fu]      = h;
        g_Ahl[fn * 64 + 32 + fu] = __float2bfloat16(v2 - __bfloat162float(h));
    }
}

// ---------------------------------------------------------------------------
// Kernel 2 (v9, mma.sync + cross terms + ldmatrix): u = hh + hm + mh.
// Grid 256 = 16 i-tiles(128) x 16 j-tiles(128). Warp w = rows w*16..+15,
// all 128 cols. A fragments (hi k0/k1, mid k0/k1) loaded ONCE per warp via
// 4 ldmatrix.x4; per nb-pair: 4 ldmatrix.x4 (B hi/mid x k0/k1) + 12 MMAs
// (hh, hm, mh). TSTRIDE=144: ldmatrix 8-row groups hit banks 0,4..28 -> CF.
// Epilogue: batched softplus (prod of 32 factors <= 2^32), quad shfl-reduce,
// diag capture, last-block ticket finalize.
// ---------------------------------------------------------------------------
#define TSTRIDE 144
__global__ void __launch_bounds__(256) jsd_kernel(float* __restrict__ out) {
    __shared__ __align__(16) char sA[128 * TSTRIDE];   // 18 KB
    __shared__ __align__(16) char sB[128 * TSTRIDE];   // 18 KB
    __shared__ unsigned s_last;

    const int tid = threadIdx.x;
    const int w = tid >> 5, lane = tid & 31;
    const int ib = blockIdx.x >> 4, q = blockIdx.x & 15;
    const int i0 = ib * 128, j0 = q * 128;

    // stage tiles: 128B rows = 8 x 16B granules
    #pragma unroll
    for (int t = 0; t < 4; t++) {
        int idx = tid + t * 256;                     // 0..1023
        int row = idx >> 3, g = idx & 7;
        *(uint4*)(sA + row * TSTRIDE + g * 16) =
            *(const uint4*)&g_Ahl[(i0 + row) * 64 + g * 8];
        *(uint4*)(sB + row * TSTRIDE + g * 16) =
            *(const uint4*)&g_Bhl[(j0 + row) * 64 + g * 8];
    }
    __syncthreads();

    const int grp = lane >> 2, four = lane & 3;      // fragment coords

    // ldmatrix source addresses (lane-dependent row + k-half offset)
    const unsigned a_row = w * 16 + (lane & 7) + ((lane >> 3) & 1) * 8;
    const unsigned a_base = smem_u32(sA) + a_row * TSTRIDE + ((lane >> 4) & 1) * 16;
    const unsigned b_col = (lane & 7) + ((lane >> 4) & 1) * 8;
    const unsigned b_base = smem_u32(sB) + b_col * TSTRIDE + ((lane >> 3) & 1) * 16;

    // A fragments: hi kstep0/1 at byte 0/32; mid kstep0/1 at 64/96
    unsigned ah0[4], ah1[4], am0[4], am1[4];
    LDM_X4(ah0, a_base + 0);
    LDM_X4(ah1, a_base + 32);
    LDM_X4(am0, a_base + 64);
    LDM_X4(am1, a_base + 96);

    float acc[16][4];
    #pragma unroll
    for (int nb = 0; nb < 16; nb++)
        #pragma unroll
        for (int p = 0; p < 4; p++) acc[nb][p] = 0.f;

    #pragma unroll
    for (int p = 0; p < 8; p++) {                    // nb pairs (16 cols each)
        unsigned bp = b_base + p * 16 * TSTRIDE;
        unsigned bh0[4], bh1[4], bm0[4], bm1[4];
        LDM_X4(bh0, bp + 0);                         // B hi  kstep0 (2 nb)
        LDM_X4(bh1, bp + 32);                        // B hi  kstep1
        LDM_X4(bm0, bp + 64);                        // B mid kstep0
        LDM_X4(bm1, bp + 96);                        // B mid kstep1
        float* c0 = acc[2 * p];
        float* c1 = acc[2 * p + 1];
        // hi.hi
        mma16816(c0, ah0, bh0);     mma16816(c1, ah0, bh0 + 2);
        mma16816(c0, ah1, bh1);     mma16816(c1, ah1, bh1 + 2);
        // hi.mid (cross)
        mma16816(c0, ah0, bm0);     mma16816(c1, ah0, bm0 + 2);
        mma16816(c0, ah1, bm1);     mma16816(c1, ah1, bm1 + 2);
        // mid.hi (cross)
        mma16816(c0, am0, bh0);     mma16816(c1, am0, bh0 + 2);
        mma16816(c0, am1, bh1);     mma16816(c1, am1, bh1 + 2);
    }

    // epilogue: rows rA (c0,c1) and rA+8 (c2,c3); cols j0+nb*8+2*four+{0,1}
    const int rA = i0 + w * 16 + grp;
    const int rB = rA + 8;
    const bool dtile = (ib == q);
    float linA = 0.f, prodA = 1.f, linB = 0.f, prodB = 1.f;
    #pragma unroll
    for (int nb = 0; nb < 16; nb++) {
        const int col = j0 + nb * 8 + 2 * four;
        float c0 = acc[nb][0], c1 = acc[nb][1];
        float c2 = acc[nb][2], c3 = acc[nb][3];
        if (dtile) {
            if (col == rA)     g_diag[rA] = c0;      // single writer each
            if (col + 1 == rA) g_diag[rA] = c1;
            if (col == rB)     g_diag[rB] = c2;
            if (col + 1 == rB) g_diag[rB] = c3;
        }
        linA  += fmaxf(c0, 0.f) + fmaxf(c1, 0.f);
        prodA *= (1.f + __expf(-fabsf(c0))) * (1.f + __expf(-fabsf(c1)));
        linB  += fmaxf(c2, 0.f) + fmaxf(c3, 0.f);
        prodB *= (1.f + __expf(-fabsf(c2))) * (1.f + __expf(-fabsf(c3)));
    }
    float sAr = linA + __logf(prodA);                // 32 softplus, 1 log
    float sBr = linB + __logf(prodB);

    // reduce across the 4 lanes of the quad sharing each row
    sAr += __shfl_xor_sync(0xffffffffu, sAr, 1);
    sAr += __shfl_xor_sync(0xffffffffu, sAr, 2);
    sBr += __shfl_xor_sync(0xffffffffu, sBr, 1);
    sBr += __shfl_xor_sync(0xffffffffu, sBr, 2);
    if (four == 0) {
        g_partial[q * NN + rA] = sAr;
        g_partial[q * NN + rB] = sBr;
    }

    // ---- last-block finalize (threadFenceReduction pattern) ----
    __threadfence();                                 // publish partials + diag
    __syncthreads();
    if (tid == 0) {
        unsigned old = atomicAdd(&g_ticket, 1u);
        s_last = ((old & 255u) == 255u) ? 1u : 0u;   // grid == 256 exactly
    }
    __syncthreads();
    if (s_last) {
        __threadfence();                             // acquire others' writes
        #pragma unroll
        for (int r = 0; r < 8; r++) {
            const int i = tid + r * 256;
            float tot = 0.f;
            #pragma unroll
            for (int p = 0; p < 16; p++) tot += g_partial[p * NN + i];
            float ud  = g_diag[i];
            float spd = softplus_f(ud);
            float Eneg = (tot - spd - 2047.f * LOG2F_) * (1.f / 2047.f);
            float Epos = LOG2F_ - spd + ud;          // = log2 - softplus(-u_ii)
            out[i]      = Eneg - Epos;               // loss
            out[NN + i] = Epos;                      // MI
        }
    }
}

extern "C" void kernel_launch(void* const* d_in, const int* in_sizes, int n_in,
                              void* d_out, int out_size) {
    const float* state  = (const float*)d_in[0];
    const float* action = (const float*)d_in[1];
    const float* W1     = (const float*)d_in[2];
    const float* b1     = (const float*)d_in[3];
    const float* W2     = (const float*)d_in[4];
    const float* b2     = (const float*)d_in[5];
    float* out = (float*)d_out;

    embed_kernel<<<NN / 4, 256>>>(state, action, W1, b1, W2, b2);
    jsd_kernel<<<256, 256>>>(out);
}